// round 17
// baseline (speedup 1.0000x reference)
#include <cuda_runtime.h>
#include <cuda_bf16.h>
#include <math.h>

// ---------------------------------------------------------------------------
// WarpNet — Round 17: pipelined GEMM (1 sync/chunk, true double buffer);
// wgt/warp kernels split across channel halves for full-chip occupancy.
// Scratch via device symbols ONLY (GB300 ATS host-shadow pitfall).
// ---------------------------------------------------------------------------

#define NIMG   4
#define CIN    512
#define HW     64
#define C1     256
#define C2     128
#define NCLS   124
#define NPAIR  2
#define NT2    1024
#define KCH    16
#define X_ELEMS (2 * NCLS * HW * HW)

typedef unsigned int u32;

// ---------------- scratch (device globals; device-code access ONLY) ---------
__device__ float g_sbuf [NIMG * C1 * HW * HW];
__device__ float g_y2   [NPAIR * HW * HW];
__device__ float g_wgt  [25 * NPAIR * HW * HW];
__device__ float g_wpart[2][26][NPAIR * HW][64];
__device__ float g_final[NPAIR * HW * HW * C1];
__device__ float g_WT   [256 * NCLS];
__device__ float g_U1[36 * CIN * C1];
__device__ float g_U2[36 * CIN * C2];
__device__ float g_M1[36 * C1 * NT2];
__device__ float g_M2[36 * C2 * NT2];
__device__ __align__(16) u32 g_A1h[36 * 2 * KCH * 2048];
__device__ __align__(16) u32 g_A1l[36 * 2 * KCH * 2048];
__device__ __align__(16) u32 g_A2h[36 * 1 * KCH * 2048];
__device__ __align__(16) u32 g_A2l[36 * 1 * KCH * 2048];
__device__ __align__(16) u32 g_Vpk[36 * NT2 * CIN];

template<int CO> __device__ __forceinline__ float* Uptr() { return (CO == C1) ? g_U1 : g_U2; }
template<int CO> __device__ __forceinline__ float* Mptr() { return (CO == C1) ? g_M1 : g_M2; }
template<int CO> __device__ __forceinline__ u32* Ahp() { return (CO == C1) ? g_A1h : g_A2h; }
template<int CO> __device__ __forceinline__ u32* Alp() { return (CO == C1) ? g_A1l : g_A2l; }

// ---------------- PTX helpers -------------------------------------------------
__device__ __forceinline__ u32 smem_u32(const void* p) {
    u32 a;
    asm("{ .reg .u64 t; cvta.to.shared.u64 t, %1; cvt.u32.u64 %0, t; }"
        : "=r"(a) : "l"(p));
    return a;
}
__device__ __forceinline__ void ldmx2(u32& r0, u32& r1, u32 addr) {
    asm volatile("ldmatrix.sync.aligned.m8n8.x2.shared.b16 {%0,%1}, [%2];"
        : "=r"(r0), "=r"(r1) : "r"(addr));
}
__device__ __forceinline__ void mma_bf16(float* d, const u32* a, const u32* b) {
    asm volatile("mma.sync.aligned.m16n8k16.row.col.f32.bf16.bf16.f32 "
        "{%0,%1,%2,%3}, {%4,%5,%6,%7}, {%8,%9}, {%0,%1,%2,%3};"
        : "+f"(d[0]), "+f"(d[1]), "+f"(d[2]), "+f"(d[3])
        : "r"(a[0]), "r"(a[1]), "r"(a[2]), "r"(a[3]), "r"(b[0]), "r"(b[1]));
}
__device__ __forceinline__ u32 bfsplit(float v, float& rem) {
    __nv_bfloat16 h = __float2bfloat16(v);
    rem = v - __bfloat162float(h);
    return (u32)__bfloat16_as_ushort(h);
}

// ---------------------------------------------------------------------------
// Winograd transforms (validated)
// ---------------------------------------------------------------------------
__device__ __forceinline__ void gxform(const float a, const float b, const float c,
                                       float* o)
{
    o[0] = 0.25f * a;
    o[1] = -(a + b + c) * (1.f / 6.f);
    o[2] = -(a - b + c) * (1.f / 6.f);
    o[3] = a * (1.f / 24.f) + b * (1.f / 12.f) + c * (1.f / 6.f);
    o[4] = a * (1.f / 24.f) - b * (1.f / 12.f) + c * (1.f / 6.f);
    o[5] = c;
}

template<int CO>
__global__ void prep_u(const float* __restrict__ W)
{
    float* U = Uptr<CO>();
    int ci = blockIdx.x, co = threadIdx.x;
    const float* g = W + ((size_t)co * CIN + ci) * 9;
    float t6[6][3];
    #pragma unroll
    for (int c = 0; c < 3; ++c) {
        float col[6];
        gxform(g[c], g[3 + c], g[6 + c], col);
        #pragma unroll
        for (int r = 0; r < 6; ++r) t6[r][c] = col[r];
    }
    #pragma unroll
    for (int r = 0; r < 6; ++r) {
        float u[6];
        gxform(t6[r][0], t6[r][1], t6[r][2], u);
        #pragma unroll
        for (int s = 0; s < 6; ++s)
            U[((size_t)(r * 6 + s) * CIN + ci) * CO + co] = u[s];
    }
}

__device__ __forceinline__ void btform(const float* d, float* o)
{
    o[0] = 4.f * d[0] - 5.f * d[2] + d[4];
    o[1] = -4.f * d[1] - 4.f * d[2] + d[3] + d[4];
    o[2] =  4.f * d[1] - 4.f * d[2] - d[3] + d[4];
    o[3] = -2.f * d[1] - d[2] + 2.f * d[3] + d[4];
    o[4] =  2.f * d[1] - d[2] - 2.f * d[3] + d[4];
    o[5] =  4.f * d[1] - 5.f * d[3] + d[5];
}

__global__ __launch_bounds__(256)
void prep_v_pk(const float* __restrict__ x)
{
    __shared__ float sM[8][36][33];

    int tgrp = blockIdx.x;
    int cig  = blockIdx.y;
    int img  = blockIdx.z;
    int t    = threadIdx.x;
    int ci_l = t >> 3, tl = t & 7;
    int tile = tgrp * 8 + tl;
    int ty = tile >> 4, tx = tile & 15;
    int ci = cig * 32 + ci_l;

    const float* p = x + ((size_t)img * CIN + ci) * HW * HW;
    int h0 = 4 * ty - 1, w0 = 4 * tx - 1;

    float d[6][6];
    #pragma unroll
    for (int r = 0; r < 6; ++r)
        #pragma unroll
        for (int c = 0; c < 6; ++c) {
            int gh = h0 + r, gw = w0 + c;
            d[r][c] = ((unsigned)gh < 64u && (unsigned)gw < 64u) ? p[gh * 64 + gw] : 0.f;
        }
    float tt[6][6];
    #pragma unroll
    for (int c = 0; c < 6; ++c) {
        float col[6], o[6];
        #pragma unroll
        for (int r = 0; r < 6; ++r) col[r] = d[r][c];
        btform(col, o);
        #pragma unroll
        for (int r = 0; r < 6; ++r) tt[r][c] = o[r];
    }
    #pragma unroll
    for (int r = 0; r < 6; ++r) {
        float o[6];
        btform(tt[r], o);
        #pragma unroll
        for (int s = 0; s < 6; ++s)
            sM[tl][r * 6 + s][ci_l] = o[s];
    }
    __syncthreads();

    #pragma unroll
    for (int r = 0; r < 36; ++r) {
        int slot = t + 256 * r;
        int row  = slot >> 5, lane = slot & 31;
        int xi = row >> 3, wtl = row & 7;
        float v = sM[wtl][xi][lane];
        float rem;
        u32 h = bfsplit(v, rem);
        __nv_bfloat16 lo = __float2bfloat16(rem);
        g_Vpk[((size_t)xi * NT2 + (img << 8) + tgrp * 8 + wtl) * CIN + cig * 32 + lane] =
            h | ((u32)__bfloat16_as_ushort(lo) << 16);
    }
}

// ---------------------------------------------------------------------------
template<int CO>
__global__ __launch_bounds__(256)
void repack_a()
{
    __shared__ float sUc[32][132];
    const float* U = Uptr<CO>();
    u32* Ah = Ahp<CO>();
    u32* Al = Alp<CO>();

    int c  = blockIdx.x;
    int cz = blockIdx.y;
    int xi = blockIdx.z;
    int t  = threadIdx.x;

    #pragma unroll
    for (int r = 0; r < 16; ++r) {
        int slot = t + 256 * r;
        int k = slot >> 7, co = slot & 127;
        sUc[k][co] = U[((size_t)xi * CIN + c * 32 + k) * CO + cz * 128 + co];
    }
    __syncthreads();

    size_t base = ((size_t)(xi * (CO / 128) + cz) * KCH + c) * 2048;
    #pragma unroll
    for (int r = 0; r < 8; ++r) {
        int slot = t + 256 * r;
        int lane = slot & 31, q = (slot >> 5) & 15, wm = slot >> 9;
        int kb = q >> 3, f = (q >> 2) & 1, reg = q & 3;
        int co = wm * 32 + f * 16 + (lane >> 2) + (reg & 1) * 8;
        int k  = kb * 16 + 2 * (lane & 3) + (reg >> 1) * 8;
        float r0, r1;
        u32 h0 = bfsplit(sUc[k][co], r0);
        u32 h1 = bfsplit(sUc[k + 1][co], r1);
        __nv_bfloat16 l0 = __float2bfloat16(r0);
        __nv_bfloat16 l1 = __float2bfloat16(r1);
        Ah[base + slot] = h0 | (h1 << 16);
        Al[base + slot] = (u32)__bfloat16_as_ushort(l0) |
                          ((u32)__bfloat16_as_ushort(l1) << 16);
    }
}

// ---------------------------------------------------------------------------
// GEMM via mma.sync, pipelined: build c+1 while mma on c, 1 sync per chunk.
// ---------------------------------------------------------------------------
#define B_TILE 8192

__device__ __forceinline__ void build_b(const u32* __restrict__ Vb, int t0, int c,
                                        int t, u32 bB)
{
    #pragma unroll
    for (int rep = 0; rep < 4; ++rep) {
        int slot = t + rep * 256;
        int bn = slot >> 3, kq = slot & 7;
        uint4 v4 = *(const uint4*)&Vb[(size_t)(t0 + bn) * CIN + c * 32 + kq * 4];
        u32 h01 = (v4.x & 0xFFFFu) | (v4.y << 16);
        u32 l01 = (v4.x >> 16) | (v4.y & 0xFFFF0000u);
        u32 h23 = (v4.z & 0xFFFFu) | (v4.w << 16);
        u32 l23 = (v4.z >> 16) | (v4.w & 0xFFFF0000u);
        u32 ad = bB + (u32)(((bn >> 3) * 4 + (kq >> 1)) * 128 +
                            (bn & 7) * 16 + (kq & 1) * 8);
        asm volatile("st.shared.v2.b32 [%0], {%1,%2};" :: "r"(ad), "r"(h01), "r"(h23) : "memory");
        asm volatile("st.shared.v2.b32 [%0], {%1,%2};" :: "r"(ad + B_TILE), "r"(l01), "r"(l23) : "memory");
    }
}

template<int CO>
__global__ __launch_bounds__(256)
void gemm_mma()
{
    __shared__ u32 sB[2 * 2 * 2048];
    const u32 sb = smem_u32(sB);

    const u32* Ah = Ahp<CO>();
    const u32* Al = Alp<CO>();
    float*     M  = Mptr<CO>();

    const int t   = threadIdx.x;
    const int l   = t & 31;
    const int wid = t >> 5;
    const int wm  = wid & 3;
    const int wn  = wid >> 2;
    const int t0  = blockIdx.x * 128;
    const int cz  = blockIdx.y;
    const int xi  = blockIdx.z;

    float acc[2][8][4];
    #pragma unroll
    for (int f = 0; f < 2; ++f)
        #pragma unroll
        for (int nf = 0; nf < 8; ++nf)
            #pragma unroll
            for (int r = 0; r < 4; ++r) acc[f][nf][r] = 0.f;

    const size_t abase = ((size_t)(xi * (CO / 128) + cz) * KCH) * 2048 + wm * 512 + l;
    const u32* Vb = g_Vpk + (size_t)xi * NT2 * CIN;
    const u32 lm_base = sb + (u32)(wn * 4096 + ((l >> 3) & 1) * 128 + (l & 7) * 16);

    u32 ah[16], al[16];
    {
        const u32* aph = Ah + abase;
        const u32* apl = Al + abase;
        #pragma unroll
        for (int q = 0; q < 16; ++q) { ah[q] = aph[q * 32]; al[q] = apl[q * 32]; }
    }
    build_b(Vb, t0, 0, t, sb);
    __syncthreads();

    for (int c = 0; c < KCH; ++c) {
        const int buf = c & 1;
        if (c + 1 < KCH)
            build_b(Vb, t0, c + 1, t, sb + (u32)(((c + 1) & 1) * 16384));

        const u32 lb = lm_base + (u32)(buf * 16384);
        #pragma unroll
        for (int kb = 0; kb < 2; ++kb) {
            #pragma unroll
            for (int nf = 0; nf < 8; ++nf) {
                u32 a = lb + (u32)(nf * 512 + kb * 256);
                u32 bh[2], bl_[2];
                ldmx2(bh[0], bh[1], a);
                ldmx2(bl_[0], bl_[1], a + B_TILE);
                #pragma unroll
                for (int f = 0; f < 2; ++f) {
                    const u32* a_h = ah + kb * 8 + f * 4;
                    const u32* a_l = al + kb * 8 + f * 4;
                    mma_bf16(acc[f][nf], a_h, bh);
                    mma_bf16(acc[f][nf], a_l, bh);
                    mma_bf16(acc[f][nf], a_h, bl_);
                }
            }
        }
        if (c + 1 < KCH) {
            const u32* aph = Ah + abase + (size_t)(c + 1) * 2048;
            const u32* apl = Al + abase + (size_t)(c + 1) * 2048;
            #pragma unroll
            for (int q = 0; q < 16; ++q) { ah[q] = aph[q * 32]; al[q] = apl[q * 32]; }
        }
        __syncthreads();
    }

    #pragma unroll
    for (int f = 0; f < 2; ++f) {
        int co = cz * 128 + wm * 32 + f * 16 + (l >> 2);
        #pragma unroll
        for (int nf = 0; nf < 8; ++nf) {
            int n0 = t0 + wn * 64 + nf * 8 + 2 * (l & 3);
            float* mb = M + ((size_t)xi * CO + co) * NT2 + n0;
            *(float2*)mb = make_float2(acc[f][nf][0], acc[f][nf][1]);
            *(float2*)(mb + 8 * (size_t)NT2) = make_float2(acc[f][nf][2], acc[f][nf][3]);
        }
    }
}

// ---------------------------------------------------------------------------
__device__ __forceinline__ void atform(const float* m, float* o)
{
    o[0] = m[0] + m[1] + m[2] + m[3] + m[4];
    o[1] = m[1] - m[2] + 2.f * (m[3] - m[4]);
    o[2] = m[1] + m[2] + 4.f * (m[3] + m[4]);
    o[3] = m[1] - m[2] + 8.f * (m[3] - m[4]) + m[5];
}

template<int CO, bool TO_SBUF>
__global__ void out_wino(const float* __restrict__ bg, const float* __restrict__ bb,
                         const float* __restrict__ bm, const float* __restrict__ bv,
                         float* __restrict__ out_ext)
{
    const float* M = Mptr<CO>();
    int co = blockIdx.y;
    int tg = blockIdx.x * 256 + threadIdx.x;

    float m[36];
    #pragma unroll
    for (int xi = 0; xi < 36; ++xi)
        m[xi] = M[((size_t)xi * CO + co) * NT2 + tg];

    float z[4][6];
    #pragma unroll
    for (int c = 0; c < 6; ++c) {
        float col[6] = {m[c], m[6 + c], m[12 + c], m[18 + c], m[24 + c], m[30 + c]};
        float o[4];
        atform(col, o);
        #pragma unroll
        for (int r = 0; r < 4; ++r) z[r][c] = o[r];
    }

    float sc = bg[co] * rsqrtf(bv[co] + 1e-5f);
    float bi = bb[co] - bm[co] * sc;

    int img = tg >> 8, tile = tg & 255;
    int ty = tile >> 4, tx = tile & 15;
    float* op = TO_SBUF ? g_sbuf : out_ext;
    float* ob = op + (((size_t)img * CO + co) * HW + 4 * ty) * HW + 4 * tx;

    #pragma unroll
    for (int r = 0; r < 4; ++r) {
        float y[4];
        atform(z[r], y);
        #pragma unroll
        for (int i = 0; i < 4; ++i) {
            float v = fmaf(y[i], sc, bi);
            y[i] = v > 0.f ? v : 0.f;
        }
        *(float4*)(ob + r * HW) = make_float4(y[0], y[1], y[2], y[3]);
    }
}

// ---------------------------------------------------------------------------
// Tail
// ---------------------------------------------------------------------------
__global__ void y2_kernel(const float* __restrict__ ce2)
{
    int nb = blockIdx.x;
    int n = nb >> 6, h = nb & 63, w = threadIdx.x;
    const float* p = ce2 + ((size_t)n * C2 * HW + h) * HW + w;
    float acc = 0.f;
    for (int c = 0; c < C2; ++c) {
        float v = p[(size_t)c * HW * HW];
        acc = fmaf(v, v, acc);
    }
    g_y2[(n * HW + h) * HW + w] = acc;
}

// wgt partial: block (nb, half); 64 channels per half.
__global__ __launch_bounds__(512)
void wgt_part(const float* __restrict__ ce2)
{
    __shared__ float s_oth[8][5][68];
    __shared__ float s_acc[26][4][64];

    int nb = blockIdx.x;
    int half = blockIdx.y;
    int n = nb >> 6, h = nb & 63;
    int t = threadIdx.x;
    int cg = t >> 6, w = t & 63;

    float acc[25];
    #pragma unroll
    for (int o = 0; o < 25; ++o) acc[o] = 0.f;
    float x2 = 0.f;

    const float* oth = ce2 + (size_t)n       * C2 * HW * HW;
    const float* c2  = ce2 + (size_t)(2 + n) * C2 * HW * HW;

    for (int c0 = half * 64; c0 < half * 64 + 64; c0 += 8) {
        __syncthreads();
        for (int e = t; e < 2720; e += 512) {
            int ec  = e / 340;
            int rem = e - ec * 340;
            int rr  = rem / 68;
            int ww  = rem - rr * 68;
            int gh  = h + rr - 2;
            int gw  = ww - 2;
            float v = 0.f;
            if ((unsigned)gh < 64u && (unsigned)gw < 64u)
                v = oth[((size_t)(c0 + ec) * HW + gh) * HW + gw];
            s_oth[ec][rr][ww] = v;
        }
        __syncthreads();

        float cv = c2[((size_t)(c0 + cg) * HW + h) * HW + w];
        x2 = fmaf(cv, cv, x2);
        #pragma unroll
        for (int o = 0; o < 25; ++o)
            acc[o] = fmaf(cv, s_oth[cg][o / 5][w + (o % 5)], acc[o]);
    }

    __syncthreads();
    if (cg >= 4) {
        #pragma unroll
        for (int o = 0; o < 25; ++o) s_acc[o][cg - 4][w] = acc[o];
        s_acc[25][cg - 4][w] = x2;
    }
    __syncthreads();
    if (cg < 4) {
        #pragma unroll
        for (int o = 0; o < 25; ++o) s_acc[o][cg][w] += acc[o];
        s_acc[25][cg][w] += x2;
    }
    __syncthreads();

    if (cg == 0) {
        #pragma unroll
        for (int o = 0; o < 26; ++o)
            g_wpart[half][o][nb][w] =
                s_acc[o][0][w] + s_acc[o][1][w] + s_acc[o][2][w] + s_acc[o][3][w];
    }
}

// wgt finish: combine halves, softmax.
__global__ void wgt_fin()
{
    int nb = blockIdx.x;
    int n = nb >> 6, h = nb & 63, w = threadIdx.x;

    float X2 = g_wpart[0][25][nb][w] + g_wpart[1][25][nb][w];
    float inv[25];
    #pragma unroll
    for (int o = 0; o < 25; ++o) {
        float cr = g_wpart[0][o][nb][w] + g_wpart[1][o][nb][w];
        int gh = h + (o / 5) - 2;
        int gw = w + (o % 5) - 2;
        float y2v = 1e20f;
        if ((unsigned)gh < 64u && (unsigned)gw < 64u)
            y2v = g_y2[(n * HW + gh) * HW + gw];
        float dist = X2 + y2v - 2.f * cr;
        inv[o] = 1.f / (dist + 1e-5f);
    }
    float m = inv[0];
    #pragma unroll
    for (int o = 1; o < 25; ++o) m = fmaxf(m, inv[o]);
    float s = 0.f;
    #pragma unroll
    for (int o = 0; o < 25; ++o) { inv[o] = expf(inv[o] - m); s += inv[o]; }
    float rs = 1.f / s;
    #pragma unroll
    for (int o = 0; o < 25; ++o)
        g_wgt[((o * NPAIR + n) * HW + h) * HW + w] = inv[o] * rs;
}

// warp: block (nb, chalf); 128 channels per half (channel-disjoint outputs).
__global__ __launch_bounds__(512)
void warp_kernel()
{
    __shared__ float s_w25[25][64];
    __shared__ float s_oth[8][5][68];

    int nb = blockIdx.x;
    int chalf = blockIdx.y;
    int n = nb >> 6, h = nb & 63;
    int t = threadIdx.x;

    for (int e = t; e < 1600; e += 512) {
        int o = e >> 6, ww = e & 63;
        s_w25[o][ww] = g_wgt[((o * NPAIR + n) * HW + h) * HW + ww];
    }

    const float* oth = g_sbuf + (size_t)n       * C1 * HW * HW;
    const float* cim = g_sbuf + (size_t)(2 + n) * C1 * HW * HW;
    int cc = t >> 6, w = t & 63;

    for (int c0 = chalf * 128; c0 < chalf * 128 + 128; c0 += 8) {
        __syncthreads();
        for (int e = t; e < 2720; e += 512) {
            int ec  = e / 340;
            int rem = e - ec * 340;
            int rr  = rem / 68;
            int ww  = rem - rr * 68;
            int gh  = h + rr - 2;
            int gw  = ww - 2;
            float v = 0.f;
            if ((unsigned)gh < 64u && (unsigned)gw < 64u)
                v = oth[((size_t)(c0 + ec) * HW + gh) * HW + gw];
            s_oth[ec][rr][ww] = v;
        }
        __syncthreads();

        float civ = cim[((size_t)(c0 + cc) * HW + h) * HW + w];
        float a = 0.f;
        #pragma unroll
        for (int o = 0; o < 25; ++o)
            a = fmaf(s_w25[o][w], s_oth[cc][o / 5][w + (o % 5)], a);
        float res = 0.5f * (civ + a * (1.0f / 25.0f));
        g_final[(((size_t)n * HW + h) * HW + w) * C1 + c0 + cc] = res;
    }
}

__global__ void wt_kernel(const float* __restrict__ lw)
{
    int o = blockIdx.x, c = threadIdx.x;
    g_WT[c * NCLS + o] = lw[o * 256 + c];
}

__global__ __launch_bounds__(128)
void head_kernel(const float* __restrict__ lb, float* __restrict__ xout)
{
    __shared__ float s_x[8][256];
    __shared__ float s_red[8][132];
    __shared__ float s_mx[8], s_ls[8];

    int pg = blockIdx.x;
    int t  = threadIdx.x;
    int l  = t & 31, wid = t >> 5;

    for (int e = t; e < 2048; e += 128) {
        int pp = e >> 8, c = e & 255;
        s_x[pp][c] = g_final[((size_t)pg * 8 + pp) * 256 + c];
    }
    __syncthreads();

    float acc[8];
    #pragma unroll
    for (int pp = 0; pp < 8; ++pp) acc[pp] = 0.f;

    if (t < NCLS) {
        for (int c = 0; c < 256; ++c) {
            float wv = g_WT[c * NCLS + t];
            #pragma unroll
            for (int pp = 0; pp < 8; ++pp)
                acc[pp] = fmaf(s_x[pp][c], wv, acc[pp]);
        }
        float bias = lb[t];
        #pragma unroll
        for (int pp = 0; pp < 8; ++pp) acc[pp] += bias;
    }

    #pragma unroll
    for (int pp = 0; pp < 8; ++pp)
        s_red[pp][t] = (t < NCLS) ? acc[pp] : -3.4e38f;
    __syncthreads();

    #pragma unroll
    for (int pp0 = 0; pp0 < 2; ++pp0) {
        int pp = wid + pp0 * 4;
        float v = fmaxf(fmaxf(s_red[pp][l], s_red[pp][l + 32]),
                        fmaxf(s_red[pp][l + 64], s_red[pp][l + 96]));
        #pragma unroll
        for (int s = 16; s > 0; s >>= 1)
            v = fmaxf(v, __shfl_xor_sync(0xFFFFFFFFu, v, s));
        if (l == 0) s_mx[pp] = v;
    }
    __syncthreads();

    #pragma unroll
    for (int pp = 0; pp < 8; ++pp)
        s_red[pp][t] = (t < NCLS) ? expf(acc[pp] - s_mx[pp]) : 0.f;
    __syncthreads();

    #pragma unroll
    for (int pp0 = 0; pp0 < 2; ++pp0) {
        int pp = wid + pp0 * 4;
        float v = s_red[pp][l] + s_red[pp][l + 32] + s_red[pp][l + 64] + s_red[pp][l + 96];
        #pragma unroll
        for (int s = 16; s > 0; s >>= 1)
            v += __shfl_xor_sync(0xFFFFFFFFu, v, s);
        if (l == 0) s_ls[pp] = s_mx[pp] + logf(v);
    }
    __syncthreads();

    if (t < NCLS) {
        #pragma unroll
        for (int pp = 0; pp < 8; ++pp) {
            int pix = pg * 8 + pp;
            int n = pix >> 12, h = (pix >> 6) & 63, w = pix & 63;
            xout[(((size_t)n * NCLS + t) * HW + h) * HW + w] = acc[pp] - s_ls[pp];
        }
    }
}

// ---------------------------------------------------------------------------
extern "C" void kernel_launch(void* const* d_in, const int* in_sizes, int n_in,
                              void* d_out, int out_size)
{
    const float* clip  = (const float*)d_in[0];
    const float* embW  = (const float*)d_in[2];
    const float* eg    = (const float*)d_in[3];
    const float* eb    = (const float*)d_in[4];
    const float* em    = (const float*)d_in[5];
    const float* ev    = (const float*)d_in[6];
    const float* emb2W = (const float*)d_in[7];
    const float* e2g   = (const float*)d_in[8];
    const float* e2b   = (const float*)d_in[9];
    const float* e2m   = (const float*)d_in[10];
    const float* e2v   = (const float*)d_in[11];
    const float* lastW = (const float*)d_in[12];
    const float* lastb = (const float*)d_in[13];

    float* xout = (float*)d_out;
    float* ce2  = (float*)d_out + X_ELEMS;

    prep_u<C1><<<CIN, C1>>>(embW);
    prep_u<C2><<<CIN, C2>>>(emb2W);
    prep_v_pk<<<dim3(32, 16, NIMG), 256>>>(clip);

    repack_a<C1><<<dim3(KCH, 2, 36), 256>>>();
    repack_a<C2><<<dim3(KCH, 1, 36), 256>>>();

    gemm_mma<C2><<<dim3(NT2 / 128, 1, 36), 256>>>();
    gemm_mma<C1><<<dim3(NT2 / 128, 2, 36), 256>>>();

    out_wino<C2, false><<<dim3(NT2 / 256, C2), 256>>>(e2g, e2b, e2m, e2v, ce2);
    out_wino<C1, true ><<<dim3(NT2 / 256, C1), 256>>>(eg, eb, em, ev, nullptr);

    y2_kernel <<<NPAIR * HW, 64>>>(ce2);
    wgt_part  <<<dim3(NPAIR * HW, 2), 512>>>(ce2);
    wgt_fin   <<<NPAIR * HW, 64>>>();
    warp_kernel<<<dim3(NPAIR * HW, 2), 512>>>();
    wt_kernel  <<<NCLS, 256>>>(lastW);
    head_kernel<<<(NPAIR * HW * HW) / 8, 128>>>(lastb, xout);
}